// round 1
// baseline (speedup 1.0000x reference)
#include <cuda_runtime.h>

// SpectrogramAugmentation: B=64, C=2, F=128, T=2048, fp32.
// inputs (metadata order): spec[B,C,F,T], apply_u[B], f_width_u[B,2], f_start_u[B,2],
//                          t_width_u[B,2], t_start_u[B,2], noise[B,C,F,T]
// out = where(apply_u<=0.5, (keep? spec:0) + 0.01*noise, spec)

#define SA_B 64
#define SA_C 2
#define SA_F 128
#define SA_T 2048
#define SA_FREQ_PARAM 20.0f
#define SA_TIME_PARAM 40.0f
#define SA_NOISE_STD 0.01f
#define SA_P_APPLY 0.5f

__global__ __launch_bounds__(256)
void specaug_kernel(const float* __restrict__ spec,
                    const float* __restrict__ apply_u,
                    const float* __restrict__ f_width_u,
                    const float* __restrict__ f_start_u,
                    const float* __restrict__ t_width_u,
                    const float* __restrict__ t_start_u,
                    const float* __restrict__ noise,
                    float* __restrict__ out) {
    const int row = blockIdx.x;                 // b*C*F + c*F + f
    const int f   = row & (SA_F - 1);
    const int b   = row / (SA_C * SA_F);
    const long long base = (long long)row * SA_T;
    const float4* __restrict__ sp4 = reinterpret_cast<const float4*>(spec + base);
    float4* __restrict__ out4      = reinterpret_cast<float4*>(out + base);
    const int tid = threadIdx.x;

    const bool apply = (apply_u[b] <= SA_P_APPLY);
    if (!apply) {
        // exact passthrough: skip the noise read entirely
        #pragma unroll
        for (int i = 0; i < SA_T / 4 / 256; i++) {
            const int idx = tid + i * 256;
            out4[idx] = sp4[idx];
        }
        return;
    }

    // --- frequency mask for this f (2 masks, no clamp_min_one) ---
    bool fhit = false;
    #pragma unroll
    for (int k = 0; k < 2; k++) {
        const int   w   = (int)floorf(f_width_u[b * 2 + k] * SA_FREQ_PARAM);
        const float rng = (float)(SA_F - w);
        const int   s0  = (int)floorf(f_start_u[b * 2 + k] * rng);
        fhit = fhit || (f >= s0 && f < s0 + w);
    }

    // --- time masks (2 masks, clamp_min_one on range) ---
    int ts0[2], te[2];
    #pragma unroll
    for (int k = 0; k < 2; k++) {
        const int   w   = (int)floorf(t_width_u[b * 2 + k] * SA_TIME_PARAM);
        float rng = (float)(SA_T - w);
        if (rng < 1.0f) rng = 1.0f;
        const int s0 = (int)floorf(t_start_u[b * 2 + k] * rng);
        ts0[k] = s0;
        te[k]  = s0 + w;
    }

    const float4* __restrict__ nz4 = reinterpret_cast<const float4*>(noise + base);

    #pragma unroll
    for (int i = 0; i < SA_T / 4 / 256; i++) {
        const int idx = tid + i * 256;
        const float4 s = sp4[idx];
        const float4 n = nz4[idx];
        const int t0 = idx * 4;
        float4 o;
        {
            const float sv[4] = {s.x, s.y, s.z, s.w};
            const float nv[4] = {n.x, n.y, n.z, n.w};
            float ov[4];
            #pragma unroll
            for (int j = 0; j < 4; j++) {
                const int t = t0 + j;
                const bool thit = (t >= ts0[0] && t < te[0]) ||
                                  (t >= ts0[1] && t < te[1]);
                const bool keep = !fhit && !thit;
                ov[j] = fmaf(nv[j], SA_NOISE_STD, keep ? sv[j] : 0.0f);
            }
            o.x = ov[0]; o.y = ov[1]; o.z = ov[2]; o.w = ov[3];
        }
        out4[idx] = o;
    }
}

extern "C" void kernel_launch(void* const* d_in, const int* in_sizes, int n_in,
                              void* d_out, int out_size) {
    const float* spec      = (const float*)d_in[0];
    const float* apply_u   = (const float*)d_in[1];
    const float* f_width_u = (const float*)d_in[2];
    const float* f_start_u = (const float*)d_in[3];
    const float* t_width_u = (const float*)d_in[4];
    const float* t_start_u = (const float*)d_in[5];
    const float* noise     = (const float*)d_in[6];
    float* out             = (float*)d_out;

    const int rows = SA_B * SA_C * SA_F;   // 16384
    specaug_kernel<<<rows, 256>>>(spec, apply_u, f_width_u, f_start_u,
                                  t_width_u, t_start_u, noise, out);
}

// round 2
// speedup vs baseline: 1.0435x; 1.0435x over previous
#include <cuda_runtime.h>

// SpectrogramAugmentation: B=64, C=2, F=128, T=2048, fp32. HBM-bound.
// Traffic minimization:
//   - non-apply batches: out = spec (no noise read)
//   - apply batches, freq-masked rows: out = 0.01*noise (no spec read)
//   - apply batches, kept rows: out = (timekeep? spec:0) + 0.01*noise
// Streaming cache hints everywhere (each byte touched once).

#define SA_B 64
#define SA_C 2
#define SA_F 128
#define SA_T 2048
#define SA_FREQ_PARAM 20.0f
#define SA_TIME_PARAM 40.0f
#define SA_NOISE_STD 0.01f
#define SA_P_APPLY 0.5f

__global__ __launch_bounds__(256)
void specaug_kernel(const float* __restrict__ spec,
                    const float* __restrict__ apply_u,
                    const float* __restrict__ f_width_u,
                    const float* __restrict__ f_start_u,
                    const float* __restrict__ t_width_u,
                    const float* __restrict__ t_start_u,
                    const float* __restrict__ noise,
                    float* __restrict__ out) {
    const int row = blockIdx.x;                 // b*C*F + c*F + f
    const int f   = row & (SA_F - 1);
    const int b   = row / (SA_C * SA_F);
    const long long base = (long long)row * SA_T;
    const float4* __restrict__ sp4 = reinterpret_cast<const float4*>(spec + base);
    float4* __restrict__ out4      = reinterpret_cast<float4*>(out + base);
    const int tid = threadIdx.x;

    const bool apply = (apply_u[b] <= SA_P_APPLY);
    if (!apply) {
        // exact passthrough: skip the noise read entirely
        #pragma unroll
        for (int i = 0; i < SA_T / 4 / 256; i++) {
            const int idx = tid + i * 256;
            __stcs(&out4[idx], __ldcs(&sp4[idx]));
        }
        return;
    }

    const float4* __restrict__ nz4 = reinterpret_cast<const float4*>(noise + base);

    // --- frequency mask for this f (2 masks, no clamp_min_one) ---
    bool fhit = false;
    #pragma unroll
    for (int k = 0; k < 2; k++) {
        const int   w   = (int)floorf(f_width_u[b * 2 + k] * SA_FREQ_PARAM);
        const float rng = (float)(SA_F - w);
        const int   s0  = (int)floorf(f_start_u[b * 2 + k] * rng);
        fhit = fhit || (f >= s0 && f < s0 + w);
    }

    if (fhit) {
        // whole row frequency-masked: out = 0.01*noise, skip spec read
        #pragma unroll
        for (int i = 0; i < SA_T / 4 / 256; i++) {
            const int idx = tid + i * 256;
            const float4 n = __ldcs(&nz4[idx]);
            float4 o;
            o.x = n.x * SA_NOISE_STD;
            o.y = n.y * SA_NOISE_STD;
            o.z = n.z * SA_NOISE_STD;
            o.w = n.w * SA_NOISE_STD;
            __stcs(&out4[idx], o);
        }
        return;
    }

    // --- time masks (2 masks, clamp_min_one on range) ---
    int ts0[2], te[2];
    #pragma unroll
    for (int k = 0; k < 2; k++) {
        const int   w   = (int)floorf(t_width_u[b * 2 + k] * SA_TIME_PARAM);
        float rng = (float)(SA_T - w);
        if (rng < 1.0f) rng = 1.0f;
        const int s0 = (int)floorf(t_start_u[b * 2 + k] * rng);
        ts0[k] = s0;
        te[k]  = s0 + w;
    }

    #pragma unroll
    for (int i = 0; i < SA_T / 4 / 256; i++) {
        const int idx = tid + i * 256;
        const float4 s = __ldcs(&sp4[idx]);
        const float4 n = __ldcs(&nz4[idx]);
        const int t0 = idx * 4;
        const float sv[4] = {s.x, s.y, s.z, s.w};
        const float nv[4] = {n.x, n.y, n.z, n.w};
        float ov[4];
        #pragma unroll
        for (int j = 0; j < 4; j++) {
            const int t = t0 + j;
            const bool thit = (t >= ts0[0] && t < te[0]) ||
                              (t >= ts0[1] && t < te[1]);
            ov[j] = fmaf(nv[j], SA_NOISE_STD, thit ? 0.0f : sv[j]);
        }
        float4 o;
        o.x = ov[0]; o.y = ov[1]; o.z = ov[2]; o.w = ov[3];
        __stcs(&out4[idx], o);
    }
}

extern "C" void kernel_launch(void* const* d_in, const int* in_sizes, int n_in,
                              void* d_out, int out_size) {
    const float* spec      = (const float*)d_in[0];
    const float* apply_u   = (const float*)d_in[1];
    const float* f_width_u = (const float*)d_in[2];
    const float* f_start_u = (const float*)d_in[3];
    const float* t_width_u = (const float*)d_in[4];
    const float* t_start_u = (const float*)d_in[5];
    const float* noise     = (const float*)d_in[6];
    float* out             = (float*)d_out;

    const int rows = SA_B * SA_C * SA_F;   // 16384
    specaug_kernel<<<rows, 256>>>(spec, apply_u, f_width_u, f_start_u,
                                  t_width_u, t_start_u, noise, out);
}